// round 5
// baseline (speedup 1.0000x reference)
#include <cuda_runtime.h>
#include <cstdint>

// ---------------------------------------------------------------------------
// Problem constants
// ---------------------------------------------------------------------------
#define NVAR 4
#define BATCH 32
#define NIN 32
#define NOUT 32
#define NFEAT 32
#define TLEN 256
#define KFILT 1024           // NOUT * NFEAT
#define M1 34                // NIN + 2
#define M2 1058              // NOUT*(NFEAT+1) + 2
#define TKN (TLEN*KFILT*NVAR)      // 1048576 = 2^20
#define KNB (KFILT*NVAR*BATCH)     // 131072

// ---------------------------------------------------------------------------
// Device scratch (no mallocs allowed)
// ---------------------------------------------------------------------------
__device__ float g_V1[NVAR*M1*NOUT];
__device__ float g_V2[NVAR*M2*NOUT];
__device__ float g_a1[NVAR*BATCH*NOUT*TLEN];            // [n][b][c][t]
__device__ float g_beta[2][NVAR][TLEN][KFILT];          // [pass][n][t][k]
__device__ float g_s0[2][KNB];                          // [pass][(k*4+n)*32+b]
__device__ float g_zpart[8][NVAR][BATCH][NOUT][TLEN];   // [kc][n][b][o][t]

// ---------------------------------------------------------------------------
// Threefry-2x32 (JAX rotation constants / key schedule), partitionable fold
// ---------------------------------------------------------------------------
__device__ __forceinline__ uint32_t rotl32(uint32_t v, int r){ return (v<<r)|(v>>(32-r)); }

__device__ __forceinline__ void tf2x32_dev(uint32_t k0, uint32_t k1,
                                           uint32_t x0, uint32_t x1,
                                           uint32_t &o0, uint32_t &o1){
  uint32_t ks2 = k0 ^ k1 ^ 0x1BD11BDAu;
  x0 += k0; x1 += k1;
#define TFR(r) { x0 += x1; x1 = rotl32(x1,(r)); x1 ^= x0; }
  TFR(13) TFR(15) TFR(26) TFR(6)  x0 += k1;  x1 += ks2 + 1u;
  TFR(17) TFR(29) TFR(16) TFR(24) x0 += ks2; x1 += k0  + 2u;
  TFR(13) TFR(15) TFR(26) TFR(6)  x0 += k0;  x1 += k1  + 3u;
  TFR(17) TFR(29) TFR(16) TFR(24) x0 += k1;  x1 += ks2 + 4u;
  TFR(13) TFR(15) TFR(26) TFR(6)  x0 += ks2; x1 += k0  + 5u;
#undef TFR
  o0 = x0; o1 = x1;
}

// uniform [0,1): partitionable random_bits = out0 ^ out1 at counter (0, idx)
__device__ __forceinline__ float tf_uniform(uint2 key, uint32_t idx){
  uint32_t a, b;
  tf2x32_dev(key.x, key.y, 0u, idx, a, b);
  uint32_t bits = a ^ b;
  return __uint_as_float((bits >> 9) | 0x3F800000u) - 1.0f;
}

// ---------------------------------------------------------------------------
// Kernel 1: effective signed-normalized weights V = thn / (sum_m |thn|+1e-10)
// grid 8 = (n, mat); 1024 threads = (o in 0..31, m-group in 0..31)
// ---------------------------------------------------------------------------
__global__ __launch_bounds__(1024) void kV(const float* __restrict__ th1,
                                           const float* __restrict__ th2,
                                           uint2 key1, uint2 key4){
  int n = blockIdx.x >> 1, mat = blockIdx.x & 1;
  int o = threadIdx.x & 31, g = threadIdx.x >> 5;
  int M = mat ? M2 : M1;
  const float* th = mat ? th2 : th1;
  uint2 key = mat ? key4 : key1;
  float* V = mat ? g_V2 : g_V1;

  float partial = 0.0f;
  for (int m = g; m < M; m += 32){
    float tv = th[m*32 + o];
    tv = fminf(fmaxf(tv, -10.0f), 10.0f);
    if (fabsf(tv) < 0.01f) tv = 0.0f;
    float u = tf_uniform(key, (uint32_t)((n*M + m)*32 + o));
    float thn = tv * ((u*2.0f - 1.0f)*0.05f + 1.0f);
    V[(n*M + m)*32 + o] = thn;       // temp store (scaled below)
    partial += fabsf(thn);
  }
  __shared__ float red[32][33];
  __shared__ float denom[32];
  red[g][o] = partial;
  __syncthreads();
  if (g == 0){
    float s = 0.0f;
    #pragma unroll
    for (int i = 0; i < 32; ++i) s += red[i][o];
    denom[o] = s + 1e-10f;
  }
  __syncthreads();
  float d = denom[o];
  for (int m = g; m < M; m += 32){
    int ii = (n*M + m)*32 + o;
    V[ii] = V[ii] / d;
  }
}

// ---------------------------------------------------------------------------
// Kernel 2: beta arrays for both filter passes + initial states s0
// ---------------------------------------------------------------------------
__global__ __launch_bounds__(256) void kBeta(const float* __restrict__ Rlf,
                                             const float* __restrict__ Clf,
                                             uint2 kRa, uint2 kCa, uint2 kMa, uint2 k0a,
                                             uint2 kRb, uint2 kCb, uint2 kMb, uint2 k0b){
  int idx = blockIdx.x*256 + threadIdx.x;
  if (idx < 2*TKN){
    int pass = idx >> 20;            // TKN == 2^20
    int rr = idx & (TKN - 1);        // ((pass*4+n)*256+t)*1024 + k
    int k = rr & 1023;
    int t = (rr >> 10) & 255;
    int nn = rr >> 18;
    uint32_t r = (uint32_t)(((t << 10) + k)*4 + nn);   // jax flat index (t,k,n)
    uint2 kR = pass ? kRb : kRa;
    uint2 kC = pass ? kCb : kCa;
    uint2 kM = pass ? kMb : kMa;
    float uR = tf_uniform(kR, r);
    float uC = tf_uniform(kC, r);
    float uM = tf_uniform(kM, r);
    float nR = (uR*2.0f - 1.0f)*0.05f + 1.0f;
    float nC = (uC*2.0f - 1.0f)*0.05f + 1.0f;
    float mu = uM*0.2f + 1.0f;
    float Rraw = Rlf[k*2 + pass];
    float Craw = Clf[k*2 + pass];
    float Rt = 1.0f/(1.0f + expf(-Rraw)) * 9900000.0f + 100000.0f;
    float Ct = 1.0f/(1.0f + expf(-Craw)) * (0.0001f - 0.0000001f) + 0.0000001f;
    float RC = mu * (Rt*nR) * (Ct*nC);
    g_beta[pass][nn][t][k] = RC / (RC + 0.1f);
  } else {
    int e = idx - 2*TKN;
    int pass = (e >= KNB) ? 1 : 0;
    uint32_t r = (uint32_t)(e - (pass ? KNB : 0));
    g_s0[pass][r] = tf_uniform(pass ? k0b : k0a, r);
  }
}

// ---------------------------------------------------------------------------
// Kernel 3: pmac1 -> a1[n][b][o][t]
// grid (b=32, n=4), 256 threads = t
// ---------------------------------------------------------------------------
__global__ __launch_bounds__(256) void kA1(const float* __restrict__ x){
  int b = blockIdx.x, n = blockIdx.y, t = threadIdx.x;
  __shared__ float V1s[33][32];    // m=0..31 weights, m=32 is bias row (M1-2)
  for (int e = t; e < 33*32; e += 256){
    int m = e >> 5, o = e & 31;
    V1s[m][o] = g_V1[(n*M1 + m)*32 + o];
  }
  __syncthreads();
  float xr[32];
  const float* xp = &x[((n*BATCH + b)*NIN)*TLEN + t];
  #pragma unroll
  for (int m = 0; m < 32; ++m) xr[m] = xp[m*TLEN];
  #pragma unroll 1
  for (int o = 0; o < 32; ++o){
    float z = V1s[32][o];
    #pragma unroll
    for (int m = 0; m < 32; ++m) z = fmaf(xr[m], V1s[m][o], z);
    g_a1[((n*BATCH + b)*NOUT + o)*TLEN + t] =
        0.05f + 0.5f*tanhf((z - 0.3f)*3.0f);
  }
}

// ---------------------------------------------------------------------------
// Kernel 4: fused 2-pass filter bank + pmac2 partial GEMM
// grid (kc=8, b=32, n=4), 128 threads; thread i owns filter k = kc*128+i
// ---------------------------------------------------------------------------
__global__ __launch_bounds__(128) void kFused(){
  int kc = blockIdx.x, b = blockIdx.y, n = blockIdx.z;
  int i = threadIdx.x;
  int k = kc*128 + i;
  int c = k >> 5;
  int f = k & 31;
  int j = c*33 + 1 + f;          // h-feature row for this filter

  __shared__ float ytile[128][33];   // [k_local][t_local], padded
  __shared__ float V2s[128][32];     // V2 rows for this chunk

  const float* vrow = &g_V2[(n*M2 + j)*32];
  #pragma unroll
  for (int o = 0; o < 32; o += 4)
    *(float4*)&V2s[i][o] = *(const float4*)&vrow[o];

  float s1 = g_s0[0][(k*4 + n)*32 + b];
  float s2 = g_s0[1][(k*4 + n)*32 + b];
  const float* b1p = &g_beta[0][n][0][k];   // stride 1024 per t
  const float* b2p = &g_beta[1][n][0][k];
  const float* xp  = &g_a1[((n*BATCH + b)*NOUT + c)*TLEN];
  float* zbase = &g_zpart[kc][n][b][0][0];

  int w = i >> 5, lane = i & 31;
  __syncthreads();

  for (int tile = 0; tile < 8; ++tile){
    int t0 = tile*32;
    // sequential recurrence for 32 timesteps (states in registers)
    #pragma unroll
    for (int tt = 0; tt < 32; ++tt){
      int t = t0 + tt;
      float bb1 = b1p[t*1024];
      float bb2 = b2p[t*1024];
      float xin = xp[t];
      ytile[i][tt] = s2;                         // y2 output at time t
      float y1 = s1;                             // pass-1 output at time t
      s2 = fmaf(bb2, s2, (1.0f - bb2)*y1);
      s1 = fmaf(bb1, s1, (1.0f - bb1)*xin);
    }
    __syncthreads();

    // tile matmul: ztile[t][o] += sum_k ytile[k][t] * V2s[k][o]
    float acc[8] = {0,0,0,0,0,0,0,0};
    #pragma unroll 4
    for (int kk = 0; kk < 128; ++kk){
      float yv = ytile[kk][lane];                          // conflict-free
      float4 vA = *(const float4*)&V2s[kk][8*w];           // warp broadcast
      float4 vB = *(const float4*)&V2s[kk][8*w + 4];
      acc[0] = fmaf(yv, vA.x, acc[0]);
      acc[1] = fmaf(yv, vA.y, acc[1]);
      acc[2] = fmaf(yv, vA.z, acc[2]);
      acc[3] = fmaf(yv, vA.w, acc[3]);
      acc[4] = fmaf(yv, vB.x, acc[4]);
      acc[5] = fmaf(yv, vB.y, acc[5]);
      acc[6] = fmaf(yv, vB.z, acc[6]);
      acc[7] = fmaf(yv, vB.w, acc[7]);
    }
    int tg = t0 + lane;
    #pragma unroll
    for (int oo = 0; oo < 8; ++oo)
      zbase[(8*w + oo)*TLEN + tg] = acc[oo];    // coalesced over lane
    __syncthreads();
  }
}

// ---------------------------------------------------------------------------
// Kernel 5: finalize pmac2: sum partials + direct a1 term + bias, activation
// grid (b=32, n=4), 256 threads = t
// ---------------------------------------------------------------------------
__global__ __launch_bounds__(256) void kFinal(float* __restrict__ out){
  int b = blockIdx.x, n = blockIdx.y, t = threadIdx.x;
  __shared__ float V2c[33][32];   // c=0..31: row j=33c (xc direct), c=32: bias row 1056
  for (int e = t; e < 33*32; e += 256){
    int c = e >> 5, o = e & 31;
    int row = (c < 32) ? c*33 : 1056;
    V2c[c][o] = g_V2[(n*M2 + row)*32 + o];
  }
  __syncthreads();
  float a1r[32];
  const float* ap = &g_a1[((n*BATCH + b)*NOUT)*TLEN + t];
  #pragma unroll
  for (int c = 0; c < 32; ++c) a1r[c] = ap[c*TLEN];

  #pragma unroll 1
  for (int o = 0; o < 32; ++o){
    float z = V2c[32][o];
    #pragma unroll
    for (int kc = 0; kc < 8; ++kc)
      z += g_zpart[kc][n][b][o][t];
    #pragma unroll
    for (int c = 0; c < 32; ++c) z = fmaf(a1r[c], V2c[c][o], z);
    out[((n*BATCH + b)*NOUT + o)*TLEN + t] =
        0.05f + 0.5f*tanhf((z - 0.3f)*3.0f);
  }
}

// ---------------------------------------------------------------------------
// Host: threefry for subkey derivation (key(42), partitionable split)
// ---------------------------------------------------------------------------
static void h_tf(uint32_t k0, uint32_t k1, uint32_t x0, uint32_t x1,
                 uint32_t &o0, uint32_t &o1){
  uint32_t ks2 = k0 ^ k1 ^ 0x1BD11BDAu;
  x0 += k0; x1 += k1;
#define HTFR(r) { x0 += x1; x1 = (x1<<(r))|(x1>>(32-(r))); x1 ^= x0; }
  HTFR(13) HTFR(15) HTFR(26) HTFR(6)  x0 += k1;  x1 += ks2 + 1u;
  HTFR(17) HTFR(29) HTFR(16) HTFR(24) x0 += ks2; x1 += k0  + 2u;
  HTFR(13) HTFR(15) HTFR(26) HTFR(6)  x0 += k0;  x1 += k1  + 3u;
  HTFR(17) HTFR(29) HTFR(16) HTFR(24) x0 += k1;  x1 += ks2 + 4u;
  HTFR(13) HTFR(15) HTFR(26) HTFR(6)  x0 += ks2; x1 += k0  + 5u;
#undef HTFR
  o0 = x0; o1 = x1;
}

static uint2 h_split(uint2 key, uint32_t i){
  uint2 r;
  h_tf(key.x, key.y, 0u, i, r.x, r.y);
  return r;
}

extern "C" void kernel_launch(void* const* d_in, const int* in_sizes, int n_in,
                              void* d_out, int out_size){
  (void)in_sizes; (void)n_in; (void)out_size;
  const float* x    = (const float*)d_in[0];
  const float* th1  = (const float*)d_in[1];
  const float* th2  = (const float*)d_in[2];
  const float* Rlf  = (const float*)d_in[3];
  const float* Clf  = (const float*)d_in[4];
  float* out = (float*)d_out;

  // key(42) -> (0,42); k1..k4 = split(root,4); filter keys = split(k2/k3, 4)
  uint2 root; root.x = 0u; root.y = 42u;
  uint2 k1 = h_split(root, 0), k2 = h_split(root, 1),
        k3 = h_split(root, 2), k4 = h_split(root, 3);
  uint2 kR1 = h_split(k2, 0), kC1 = h_split(k2, 1),
        kM1 = h_split(k2, 2), k01 = h_split(k2, 3);
  uint2 kR2 = h_split(k3, 0), kC2 = h_split(k3, 1),
        kM2 = h_split(k3, 2), k02 = h_split(k3, 3);

  kV<<<8, 1024>>>(th1, th2, k1, k4);
  kBeta<<<(2*TKN + 2*KNB)/256, 256>>>(Rlf, Clf,
                                      kR1, kC1, kM1, k01,
                                      kR2, kC2, kM2, k02);
  kA1<<<dim3(BATCH, NVAR), 256>>>(x);
  kFused<<<dim3(8, BATCH, NVAR), 128>>>();
  kFinal<<<dim3(BATCH, NVAR), 256>>>(out);
}

// round 7
// speedup vs baseline: 1.0080x; 1.0080x over previous
#include <cuda_runtime.h>
#include <cstdint>

// ---------------------------------------------------------------------------
// Problem constants
// ---------------------------------------------------------------------------
#define NVAR 4
#define BATCH 32
#define NIN 32
#define NOUT 32
#define NFEAT 32
#define TLEN 256
#define KFILT 1024           // NOUT * NFEAT
#define M1 34                // NIN + 2
#define M2 1058              // NOUT*(NFEAT+1) + 2
#define TKN (TLEN*KFILT*NVAR)      // 1048576 = 2^20
#define KNB (KFILT*NVAR*BATCH)     // 131072

// dynamic smem for kFused: ytile[128][65] + V2s[128][32]
#define SMEM_FUSED ((128*65 + 128*32)*4)

// ---------------------------------------------------------------------------
// Device scratch (no mallocs allowed)
// ---------------------------------------------------------------------------
__device__ float g_V1[NVAR*M1*NOUT];
__device__ float g_V2[NVAR*M2*NOUT];
__device__ float g_a1[NVAR*BATCH*NOUT*TLEN];            // [n][b][c][t]
__device__ float g_beta[2][NVAR][TLEN][KFILT];          // [pass][n][t][k]
__device__ float g_s0[2][KNB];                          // [pass][(k*4+n)*32+b]
__device__ float g_RC[2][KFILT];                        // Rt*Ct per (pass,k)
__device__ float g_zpart[8][NVAR][BATCH][NOUT][TLEN];   // [kc][n][b][o][t]

// ---------------------------------------------------------------------------
// Packed f32x2 helpers (sm_103a FFMA2)
// ---------------------------------------------------------------------------
__device__ __forceinline__ uint64_t dup2(float v){
  uint64_t r; asm("mov.b64 %0, {%1, %1};" : "=l"(r) : "f"(v)); return r;
}
__device__ __forceinline__ void fma2(uint64_t &acc, uint64_t a, uint64_t b){
  asm("fma.rn.f32x2 %0, %1, %2, %0;" : "+l"(acc) : "l"(a), "l"(b));
}
__device__ __forceinline__ float2 unpk(uint64_t v){
  float2 r; asm("mov.b64 {%0, %1}, %2;" : "=f"(r.x), "=f"(r.y) : "l"(v)); return r;
}

// ---------------------------------------------------------------------------
// Threefry-2x32 (JAX rotation constants / key schedule), partitionable fold
// ---------------------------------------------------------------------------
__device__ __forceinline__ uint32_t rotl32(uint32_t v, int r){ return (v<<r)|(v>>(32-r)); }

__device__ __forceinline__ void tf2x32_dev(uint32_t k0, uint32_t k1,
                                           uint32_t x0, uint32_t x1,
                                           uint32_t &o0, uint32_t &o1){
  uint32_t ks2 = k0 ^ k1 ^ 0x1BD11BDAu;
  x0 += k0; x1 += k1;
#define TFR(r) { x0 += x1; x1 = rotl32(x1,(r)); x1 ^= x0; }
  TFR(13) TFR(15) TFR(26) TFR(6)  x0 += k1;  x1 += ks2 + 1u;
  TFR(17) TFR(29) TFR(16) TFR(24) x0 += ks2; x1 += k0  + 2u;
  TFR(13) TFR(15) TFR(26) TFR(6)  x0 += k0;  x1 += k1  + 3u;
  TFR(17) TFR(29) TFR(16) TFR(24) x0 += k1;  x1 += ks2 + 4u;
  TFR(13) TFR(15) TFR(26) TFR(6)  x0 += ks2; x1 += k0  + 5u;
#undef TFR
  o0 = x0; o1 = x1;
}

// uniform [0,1): partitionable random_bits = out0 ^ out1 at counter (0, idx)
__device__ __forceinline__ float tf_uniform(uint2 key, uint32_t idx){
  uint32_t a, b;
  tf2x32_dev(key.x, key.y, 0u, idx, a, b);
  uint32_t bits = a ^ b;
  return __uint_as_float((bits >> 9) | 0x3F800000u) - 1.0f;
}

// ---------------------------------------------------------------------------
// Kernel 1: effective signed-normalized weights V = thn / (sum_m |thn|+1e-10)
// grid 8 = (n, mat); 1024 threads = (o in 0..31, m-group in 0..31)
// ---------------------------------------------------------------------------
__global__ __launch_bounds__(1024) void kV(const float* __restrict__ th1,
                                           const float* __restrict__ th2,
                                           uint2 key1, uint2 key4){
  int n = blockIdx.x >> 1, mat = blockIdx.x & 1;
  int o = threadIdx.x & 31, g = threadIdx.x >> 5;
  int M = mat ? M2 : M1;
  const float* th = mat ? th2 : th1;
  uint2 key = mat ? key4 : key1;
  float* V = mat ? g_V2 : g_V1;

  float partial = 0.0f;
  for (int m = g; m < M; m += 32){
    float tv = th[m*32 + o];
    tv = fminf(fmaxf(tv, -10.0f), 10.0f);
    if (fabsf(tv) < 0.01f) tv = 0.0f;
    float u = tf_uniform(key, (uint32_t)((n*M + m)*32 + o));
    float thn = tv * ((u*2.0f - 1.0f)*0.05f + 1.0f);
    V[(n*M + m)*32 + o] = thn;       // temp store (scaled below)
    partial += fabsf(thn);
  }
  __shared__ float red[32][33];
  __shared__ float denom[32];
  red[g][o] = partial;
  __syncthreads();
  if (g == 0){
    float s = 0.0f;
    #pragma unroll
    for (int i = 0; i < 32; ++i) s += red[i][o];
    denom[o] = s + 1e-10f;
  }
  __syncthreads();
  float d = denom[o];
  for (int m = g; m < M; m += 32){
    int ii = (n*M + m)*32 + o;
    V[ii] = V[ii] / d;
  }
}

// ---------------------------------------------------------------------------
// Kernel 1b: precompute Rt*Ct per (pass, k)  (hoists 2x expf out of kBeta)
// ---------------------------------------------------------------------------
__global__ __launch_bounds__(256) void kRC(const float* __restrict__ Rlf,
                                           const float* __restrict__ Clf){
  int idx = blockIdx.x*256 + threadIdx.x;      // 2048 total
  if (idx >= 2*KFILT) return;
  int k = idx >> 1, pass = idx & 1;
  float Rraw = Rlf[k*2 + pass];
  float Craw = Clf[k*2 + pass];
  float Rt = 1.0f/(1.0f + expf(-Rraw)) * 9900000.0f + 100000.0f;
  float Ct = 1.0f/(1.0f + expf(-Craw)) * (0.0001f - 0.0000001f) + 0.0000001f;
  g_RC[pass][k] = Rt * Ct;
}

// ---------------------------------------------------------------------------
// Kernel 2: beta arrays for both filter passes + initial states s0
// ---------------------------------------------------------------------------
__global__ __launch_bounds__(256) void kBeta(uint2 kRa, uint2 kCa, uint2 kMa, uint2 k0a,
                                             uint2 kRb, uint2 kCb, uint2 kMb, uint2 k0b){
  int idx = blockIdx.x*256 + threadIdx.x;
  if (idx < 2*TKN){
    int pass = idx >> 20;            // TKN == 2^20
    int rr = idx & (TKN - 1);        // ((pass*4+n)*256+t)*1024 + k
    int k = rr & 1023;
    int t = (rr >> 10) & 255;
    int nn = rr >> 18;
    uint32_t r = (uint32_t)(((t << 10) + k)*4 + nn);   // jax flat index (t,k,n)
    uint2 kR = pass ? kRb : kRa;
    uint2 kC = pass ? kCb : kCa;
    uint2 kM = pass ? kMb : kMa;
    float uR = tf_uniform(kR, r);
    float uC = tf_uniform(kC, r);
    float uM = tf_uniform(kM, r);
    float nR = (uR*2.0f - 1.0f)*0.05f + 1.0f;
    float nC = (uC*2.0f - 1.0f)*0.05f + 1.0f;
    float mu = uM*0.2f + 1.0f;
    float RC = mu * g_RC[pass][k] * nR * nC;
    g_beta[pass][nn][t][k] = RC / (RC + 0.1f);
  } else {
    int e = idx - 2*TKN;
    int pass = (e >= KNB) ? 1 : 0;
    uint32_t r = (uint32_t)(e - (pass ? KNB : 0));
    g_s0[pass][r] = tf_uniform(pass ? k0b : k0a, r);
  }
}

// ---------------------------------------------------------------------------
// Kernel 3: pmac1 -> a1[n][b][o][t]
// grid (b=32, n=4), 256 threads = t
// ---------------------------------------------------------------------------
__global__ __launch_bounds__(256) void kA1(const float* __restrict__ x){
  int b = blockIdx.x, n = blockIdx.y, t = threadIdx.x;
  __shared__ float V1s[33][32];    // m=0..31 weights, m=32 is bias row (M1-2)
  for (int e = t; e < 33*32; e += 256){
    int m = e >> 5, o = e & 31;
    V1s[m][o] = g_V1[(n*M1 + m)*32 + o];
  }
  __syncthreads();
  float xr[32];
  const float* xp = &x[((n*BATCH + b)*NIN)*TLEN + t];
  #pragma unroll
  for (int m = 0; m < 32; ++m) xr[m] = xp[m*TLEN];
  #pragma unroll 1
  for (int o = 0; o < 32; ++o){
    float z = V1s[32][o];
    #pragma unroll
    for (int m = 0; m < 32; ++m) z = fmaf(xr[m], V1s[m][o], z);
    g_a1[((n*BATCH + b)*NOUT + o)*TLEN + t] =
        0.05f + 0.5f*tanhf((z - 0.3f)*3.0f);
  }
}

// ---------------------------------------------------------------------------
// Kernel 4: fused 2-pass filter bank + pmac2 partial GEMM (packed f32x2)
// grid (kc=8, b=32, n=4), 128 threads; thread i owns filter k = kc*128+i
// t-tile = 64; each thread computes 8 o's x 2 t's, accs packed over o-pairs
// ---------------------------------------------------------------------------
__global__ __launch_bounds__(128) void kFused(){
  int kc = blockIdx.x, b = blockIdx.y, n = blockIdx.z;
  int i = threadIdx.x;
  int k = kc*128 + i;
  int c = k >> 5;
  int f = k & 31;
  int j = c*33 + 1 + f;          // h-feature row for this filter

  extern __shared__ float sm[];
  float (*ytile)[65] = (float(*)[65])sm;            // [k_local][t_local]
  float (*V2s)[32]   = (float(*)[32])(sm + 128*65); // V2 rows, 16B-aligned

  const float* vrow = &g_V2[(n*M2 + j)*32];
  #pragma unroll
  for (int o = 0; o < 32; o += 4)
    *(float4*)&V2s[i][o] = *(const float4*)&vrow[o];

  float s1 = g_s0[0][(k*4 + n)*32 + b];
  float s2 = g_s0[1][(k*4 + n)*32 + b];
  const float* b1p = &g_beta[0][n][0][k];   // stride 1024 per t
  const float* b2p = &g_beta[1][n][0][k];
  const float* xp  = &g_a1[((n*BATCH + b)*NOUT + c)*TLEN];
  float* zbase = &g_zpart[kc][n][b][0][0];

  int w = i >> 5, lane = i & 31;
  __syncthreads();

  for (int tile = 0; tile < 4; ++tile){
    int t0 = tile*64;
    // sequential recurrence for 64 timesteps (states in registers)
    #pragma unroll
    for (int tt = 0; tt < 64; ++tt){
      int t = t0 + tt;
      float bb1 = b1p[t*1024];
      float bb2 = b2p[t*1024];
      float xin = xp[t];
      ytile[i][tt] = s2;                         // y2 output at time t
      float y1 = s1;                             // pass-1 output at time t
      s2 = fmaf(bb2, s2, (1.0f - bb2)*y1);
      s1 = fmaf(bb1, s1, (1.0f - bb1)*xin);
    }
    __syncthreads();

    // tile matmul: z[t][o] += sum_k ytile[k][t] * V2s[k][o]
    // accs packed over o-pairs; t_a = lane, t_b = lane+32
    uint64_t acc[8] = {0,0,0,0,0,0,0,0};
    #pragma unroll 2
    for (int kk = 0; kk < 128; ++kk){
      float ya = ytile[kk][lane];                      // conflict-free
      float yb = ytile[kk][lane + 32];
      uint64_t y2a = dup2(ya);
      uint64_t y2b = dup2(yb);
      ulonglong2 v0 = *(const ulonglong2*)&V2s[kk][8*w];     // {v0v1, v2v3}
      ulonglong2 v1 = *(const ulonglong2*)&V2s[kk][8*w + 4]; // {v4v5, v6v7}
      fma2(acc[0], y2a, v0.x);  fma2(acc[4], y2b, v0.x);
      fma2(acc[1], y2a, v0.y);  fma2(acc[5], y2b, v0.y);
      fma2(acc[2], y2a, v1.x);  fma2(acc[6], y2b, v1.x);
      fma2(acc[3], y2a, v1.y);  fma2(acc[7], y2b, v1.y);
    }
    int ta = t0 + lane;
    int tb = ta + 32;
    #pragma unroll
    for (int p = 0; p < 4; ++p){
      float2 ra = unpk(acc[p]);
      float2 rb = unpk(acc[4 + p]);
      zbase[(8*w + 2*p    )*TLEN + ta] = ra.x;   // coalesced over lane
      zbase[(8*w + 2*p + 1)*TLEN + ta] = ra.y;
      zbase[(8*w + 2*p    )*TLEN + tb] = rb.x;
      zbase[(8*w + 2*p + 1)*TLEN + tb] = rb.y;
    }
    __syncthreads();
  }
}

// ---------------------------------------------------------------------------
// Kernel 5: finalize pmac2: sum partials + direct a1 term + bias, activation
// grid (b=32, n=4), 256 threads = t
// ---------------------------------------------------------------------------
__global__ __launch_bounds__(256) void kFinal(float* __restrict__ out){
  int b = blockIdx.x, n = blockIdx.y, t = threadIdx.x;
  __shared__ float V2c[33][32];   // c=0..31: row j=33c (xc direct), c=32: bias row 1056
  for (int e = t; e < 33*32; e += 256){
    int c = e >> 5, o = e & 31;
    int row = (c < 32) ? c*33 : 1056;
    V2c[c][o] = g_V2[(n*M2 + row)*32 + o];
  }
  __syncthreads();
  float a1r[32];
  const float* ap = &g_a1[((n*BATCH + b)*NOUT)*TLEN + t];
  #pragma unroll
  for (int c = 0; c < 32; ++c) a1r[c] = ap[c*TLEN];

  #pragma unroll 1
  for (int o = 0; o < 32; ++o){
    float z = V2c[32][o];
    #pragma unroll
    for (int kc = 0; kc < 8; ++kc)
      z += g_zpart[kc][n][b][o][t];
    #pragma unroll
    for (int c = 0; c < 32; ++c) z = fmaf(a1r[c], V2c[c][o], z);
    out[((n*BATCH + b)*NOUT + o)*TLEN + t] =
        0.05f + 0.5f*tanhf((z - 0.3f)*3.0f);
  }
}

// ---------------------------------------------------------------------------
// Host: threefry for subkey derivation (key(42), partitionable split)
// ---------------------------------------------------------------------------
static void h_tf(uint32_t k0, uint32_t k1, uint32_t x0, uint32_t x1,
                 uint32_t &o0, uint32_t &o1){
  uint32_t ks2 = k0 ^ k1 ^ 0x1BD11BDAu;
  x0 += k0; x1 += k1;
#define HTFR(r) { x0 += x1; x1 = (x1<<(r))|(x1>>(32-(r))); x1 ^= x0; }
  HTFR(13) HTFR(15) HTFR(26) HTFR(6)  x0 += k1;  x1 += ks2 + 1u;
  HTFR(17) HTFR(29) HTFR(16) HTFR(24) x0 += ks2; x1 += k0  + 2u;
  HTFR(13) HTFR(15) HTFR(26) HTFR(6)  x0 += k0;  x1 += k1  + 3u;
  HTFR(17) HTFR(29) HTFR(16) HTFR(24) x0 += k1;  x1 += ks2 + 4u;
  HTFR(13) HTFR(15) HTFR(26) HTFR(6)  x0 += ks2; x1 += k0  + 5u;
#undef HTFR
  o0 = x0; o1 = x1;
}

static uint2 h_split(uint2 key, uint32_t i){
  uint2 r;
  h_tf(key.x, key.y, 0u, i, r.x, r.y);
  return r;
}

extern "C" void kernel_launch(void* const* d_in, const int* in_sizes, int n_in,
                              void* d_out, int out_size){
  (void)in_sizes; (void)n_in; (void)out_size;
  const float* x    = (const float*)d_in[0];
  const float* th1  = (const float*)d_in[1];
  const float* th2  = (const float*)d_in[2];
  const float* Rlf  = (const float*)d_in[3];
  const float* Clf  = (const float*)d_in[4];
  float* out = (float*)d_out;

  // key(42) -> (0,42); k1..k4 = split(root,4); filter keys = split(k2/k3, 4)
  uint2 root; root.x = 0u; root.y = 42u;
  uint2 k1 = h_split(root, 0), k2 = h_split(root, 1),
        k3 = h_split(root, 2), k4 = h_split(root, 3);
  uint2 kR1 = h_split(k2, 0), kC1 = h_split(k2, 1),
        kM1 = h_split(k2, 2), k01 = h_split(k2, 3);
  uint2 kR2 = h_split(k3, 0), kC2 = h_split(k3, 1),
        kM2 = h_split(k3, 2), k02 = h_split(k3, 3);

  cudaFuncSetAttribute(kFused, cudaFuncAttributeMaxDynamicSharedMemorySize,
                       SMEM_FUSED);

  kV<<<8, 1024>>>(th1, th2, k1, k4);
  kRC<<<8, 256>>>(Rlf, Clf);
  kBeta<<<(2*TKN + 2*KNB)/256, 256>>>(kR1, kC1, kM1, k01,
                                      kR2, kC2, kM2, k02);
  kA1<<<dim3(BATCH, NVAR), 256>>>(x);
  kFused<<<dim3(8, BATCH, NVAR), 128, SMEM_FUSED>>>();
  kFinal<<<dim3(BATCH, NVAR), 256>>>(out);
}